// round 5
// baseline (speedup 1.0000x reference)
#include <cuda_runtime.h>
#include <cuda_bf16.h>
#include <math.h>

// ---------------------------------------------------------------------------
// SwinV2 block. Round 3: all four GEMMs on tensor cores (tf32 mma.sync).
// B=8, C=192, H=W=128, HEADS=6, WS=8, SHIFT=4, N=64, HIDDEN=768
// ---------------------------------------------------------------------------

#define TOK   131072
#define CCH   192
#define HEADS 6
#define HDIM  32
#define NWIN  2048
#define HID   768

__device__ float g_xw  [ (size_t)TOK * CCH ];
__device__ float g_qkv [ (size_t)TOK * 576 ];
__device__ float g_ao  [ (size_t)TOK * CCH ];
__device__ float g_x1  [ (size_t)TOK * CCH ];
__device__ float g_h   [ (size_t)TOK * HID ];
__device__ float g_table [ 225 * HEADS ];
__device__ float g_rpbias[ HEADS * 64 * 64 ];

// ---------------------------------------------------------------------------
__device__ __forceinline__ float relcoord(int ci) {
    float v = (float)(ci - 7) * (8.0f / 7.0f);
    float r = log2f(fabsf(v) + 1.0f) * (1.0f / 3.0f);
    return (v < 0.0f) ? -r : r;
}

__global__ void cpb_table_kernel(const float* __restrict__ w1,
                                 const float* __restrict__ b1,
                                 const float* __restrict__ w2) {
    __shared__ float hid[512];
    int pos = blockIdx.x;
    int a = pos / 15, b = pos % 15;
    float r0 = relcoord(a), r1 = relcoord(b);
    int u = threadIdx.x;
    hid[u] = fmaxf(0.0f, r0 * w1[2 * u] + r1 * w1[2 * u + 1] + b1[u]);
    __syncthreads();
    int warp = u >> 5, lane = u & 31;
    if (warp < HEADS) {
        float s = 0.0f;
        #pragma unroll
        for (int k = 0; k < 16; k++) {
            int uu = lane + (k << 5);
            s += hid[uu] * w2[warp * 512 + uu];
        }
        #pragma unroll
        for (int off = 16; off > 0; off >>= 1)
            s += __shfl_xor_sync(0xffffffffu, s, off);
        if (lane == 0) g_table[pos * HEADS + warp] = s;
    }
}

__global__ void rpbias_kernel() {
    int e = blockIdx.x * blockDim.x + threadIdx.x;
    int h = e >> 12;
    int rem = e & 4095;
    int i = rem >> 6, j = rem & 63;
    int d0 = (i >> 3) - (j >> 3) + 7;
    int d1 = (i & 7) - (j & 7) + 7;
    float t = g_table[(d0 * 15 + d1) * HEADS + h];
    g_rpbias[e] = 16.0f / (1.0f + expf(-t));
}

// ---------------------------------------------------------------------------
__global__ void ln1_kernel(const float* __restrict__ x,
                           const float* __restrict__ nw,
                           const float* __restrict__ nb) {
    __shared__ float s[32][193];
    __shared__ float smu[32], srs[32];
    int tid = threadIdx.x;
    int t0 = blockIdx.x << 5;

    for (int e = tid; e < 32 * 192; e += 192) {
        int tk = e & 31;
        int c  = e >> 5;
        int t  = t0 + tk;
        int win = t >> 6, n = t & 63;
        int b = win >> 8, wi = win & 255;
        int h = ((((wi >> 4) << 3) + (n >> 3)) + 4) & 127;
        int w = ((((wi & 15) << 3) + (n & 7)) + 4) & 127;
        s[tk][c] = x[(((size_t)b * CCH + c) << 14) + (h << 7) + w];
    }
    __syncthreads();
    if (tid < 32) {
        float sum = 0.0f, sq = 0.0f;
        #pragma unroll 4
        for (int c = 0; c < 192; c++) { float v = s[tid][c]; sum += v; sq += v * v; }
        float mu = sum * (1.0f / 192.0f);
        float var = sq * (1.0f / 192.0f) - mu * mu;
        smu[tid] = mu;
        srs[tid] = rsqrtf(var + 1e-5f);
    }
    __syncthreads();
    int c = tid;
    float wv = nw[c], bv = nb[c];
    #pragma unroll 4
    for (int tk = 0; tk < 32; tk++) {
        g_xw[(size_t)(t0 + tk) * CCH + c] = (s[tk][c] - smu[tk]) * srs[tk] * wv + bv;
    }
}

__global__ void ln2_kernel(const float* __restrict__ nw,
                           const float* __restrict__ nb) {
    int warp = threadIdx.x >> 5, lane = threadIdx.x & 31;
    int p = (blockIdx.x << 3) + warp;
    const float* row = g_x1 + (size_t)p * CCH;
    float v[6];
    float sum = 0.0f, sq = 0.0f;
    #pragma unroll
    for (int k = 0; k < 6; k++) {
        v[k] = row[lane + (k << 5)];
        sum += v[k]; sq += v[k] * v[k];
    }
    #pragma unroll
    for (int off = 16; off > 0; off >>= 1) {
        sum += __shfl_xor_sync(0xffffffffu, sum, off);
        sq  += __shfl_xor_sync(0xffffffffu, sq,  off);
    }
    float mu = sum * (1.0f / 192.0f);
    float rstd = rsqrtf(sq * (1.0f / 192.0f) - mu * mu + 1e-5f);
    float* out = g_xw + (size_t)p * CCH;
    #pragma unroll
    for (int k = 0; k < 6; k++) {
        int c = lane + (k << 5);
        out[c] = (v[k] - mu) * rstd * nw[c] + nb[c];
    }
}

// ---------------------------------------------------------------------------
__device__ __forceinline__ int swin_region(int v) {
    return (v < 120) ? 0 : ((v < 124) ? 1 : 2);
}

__global__ void attn_kernel(const float* __restrict__ logit_scale) {
    __shared__ __align__(16) float sq[64][36];
    __shared__ __align__(16) float sk[64][36];
    __shared__ __align__(16) float sv[64][36];
    __shared__ float sS[64][65];
    __shared__ int sreg[64];

    int head = blockIdx.x;
    int wg   = blockIdx.y;
    int tid  = threadIdx.x;
    int t0   = wg << 6;
    int wi   = wg & 255;
    int wh   = wi >> 4, ww = wi & 15;

    for (int e = tid; e < 2048; e += 128) {
        int n = e >> 5, d = e & 31;
        size_t g = (size_t)(t0 + n) * 576 + (head << 5) + d;
        sq[n][d] = g_qkv[g];
        sk[n][d] = g_qkv[g + 192];
        sv[n][d] = g_qkv[g + 384];
    }
    __syncthreads();

    float ls = expf(fminf(logit_scale[head], 4.6051701859880914f));

    if (tid < 64) {
        int r = tid;
        float s = 0.0f;
        #pragma unroll
        for (int d = 0; d < 32; d++) s += sq[r][d] * sq[r][d];
        float sc = ls / fmaxf(sqrtf(s), 1e-12f);
        #pragma unroll
        for (int d = 0; d < 32; d++) sq[r][d] *= sc;
        int hs = (wh << 3) + (r >> 3);
        int ws_ = (ww << 3) + (r & 7);
        sreg[r] = 3 * swin_region(hs) + swin_region(ws_);
    } else {
        int r = tid - 64;
        float s = 0.0f;
        #pragma unroll
        for (int d = 0; d < 32; d++) s += sk[r][d] * sk[r][d];
        float sc = 1.0f / fmaxf(sqrtf(s), 1e-12f);
        #pragma unroll
        for (int d = 0; d < 32; d++) sk[r][d] *= sc;
    }
    __syncthreads();

    #pragma unroll 1
    for (int it = 0; it < 32; it++) {
        int s = tid + (it << 7);
        int i = s >> 6, j = s & 63;
        const float4* qv = (const float4*)sq[i];
        const float4* kv = (const float4*)sk[j];
        float acc = 0.0f;
        #pragma unroll
        for (int d = 0; d < 8; d++) {
            float4 a = qv[d], b = kv[d];
            acc += a.x * b.x + a.y * b.y + a.z * b.z + a.w * b.w;
        }
        acc += g_rpbias[(head << 12) + (i << 6) + j];
        if (sreg[i] != sreg[j]) acc -= 100.0f;
        sS[i][j] = acc;
    }
    __syncthreads();

    if (tid < 64) {
        int r = tid;
        float m = -1e30f;
        #pragma unroll 4
        for (int j = 0; j < 64; j++) m = fmaxf(m, sS[r][j]);
        float sum = 0.0f;
        #pragma unroll 4
        for (int j = 0; j < 64; j++) { float e = expf(sS[r][j] - m); sS[r][j] = e; sum += e; }
        float inv = 1.0f / sum;
        #pragma unroll 4
        for (int j = 0; j < 64; j++) sS[r][j] *= inv;
    }
    __syncthreads();

    #pragma unroll 1
    for (int it = 0; it < 16; it++) {
        int e = tid + (it << 7);
        int i = e >> 5, d = e & 31;
        float acc = 0.0f;
        #pragma unroll
        for (int j = 0; j < 64; j++) acc += sS[i][j] * sv[j][d];
        g_ao[(size_t)(t0 + i) * CCH + (head << 5) + d] = acc;
    }
}

// ---------------------------------------------------------------------------
// Tensor-core GEMM: out[M x NC] = A[M x K] @ W[NC x K]^T  (+ epilogue)
// BM=128, BN=64, BK=32, 256 threads (8 warps, 4x2), warp tile 32x32,
// mma.sync.aligned.m16n8k8 tf32, fp32 accumulate.
// ---------------------------------------------------------------------------
__device__ __forceinline__ unsigned f2tf32(float f) {
    unsigned r;
    asm("cvt.rna.tf32.f32 %0, %1;" : "=r"(r) : "f"(f));
    return r;
}

__device__ __forceinline__ void mma_tf32(float* c, const unsigned* a, const unsigned* b) {
    asm volatile(
        "mma.sync.aligned.m16n8k8.row.col.f32.tf32.tf32.f32 "
        "{%0,%1,%2,%3}, {%4,%5,%6,%7}, {%8,%9}, {%0,%1,%2,%3};"
        : "+f"(c[0]), "+f"(c[1]), "+f"(c[2]), "+f"(c[3])
        : "r"(a[0]), "r"(a[1]), "r"(a[2]), "r"(a[3]), "r"(b[0]), "r"(b[1]));
}

template <int MODE>
__global__ void __launch_bounds__(256) gemm_kernel(const float* __restrict__ W,
                                                   const float* __restrict__ bias,
                                                   const float* __restrict__ bias2,
                                                   const float* __restrict__ aux,
                                                   float* __restrict__ outext) {
    constexpr int K  = (MODE == 3) ? 768 : 192;
    constexpr int NK = K >> 5;

    const float* A = (MODE == 0 || MODE == 2) ? g_xw : (MODE == 1 ? g_ao : g_h);

    __shared__ __align__(16) float As[128][36];
    __shared__ __align__(16) float Bs[64][36];

    int tid = threadIdx.x;
    int m0 = blockIdx.y << 7;
    int o0 = blockIdx.x << 6;
    const float* Ab = A + (size_t)m0 * K;
    const float* Wb = W + (size_t)o0 * K;

    int ar = tid >> 3;            // 0..31
    int ac = (tid & 7) << 2;      // 0,4,...,28

    float4 pa[4], pb[2];
    #pragma unroll
    for (int p = 0; p < 4; p++)
        pa[p] = *(const float4*)&Ab[(size_t)(ar + (p << 5)) * K + ac];
    #pragma unroll
    for (int p = 0; p < 2; p++)
        pb[p] = *(const float4*)&Wb[(size_t)(ar + (p << 5)) * K + ac];

    int warp = tid >> 5;
    int lane = tid & 31;
    int wm = (warp & 3) << 5;     // warp M offset within block (4 warps)
    int wn = (warp >> 2) << 5;    // warp N offset within block (2 warps)
    int gq = lane >> 2;           // groupID 0..7
    int tg = lane & 3;            // threadID_in_group 0..3

    float acc[2][4][4];
    #pragma unroll
    for (int mt = 0; mt < 2; mt++)
        #pragma unroll
        for (int nt = 0; nt < 4; nt++)
            #pragma unroll
            for (int r = 0; r < 4; r++) acc[mt][nt][r] = 0.0f;

    #pragma unroll 1
    for (int kt = 0; kt < NK; kt++) {
        #pragma unroll
        for (int p = 0; p < 4; p++)
            *(float4*)&As[ar + (p << 5)][ac] = pa[p];
        #pragma unroll
        for (int p = 0; p < 2; p++)
            *(float4*)&Bs[ar + (p << 5)][ac] = pb[p];
        __syncthreads();
        if (kt + 1 < NK) {
            int k0 = (kt + 1) << 5;
            #pragma unroll
            for (int p = 0; p < 4; p++)
                pa[p] = *(const float4*)&Ab[(size_t)(ar + (p << 5)) * K + k0 + ac];
            #pragma unroll
            for (int p = 0; p < 2; p++)
                pb[p] = *(const float4*)&Wb[(size_t)(ar + (p << 5)) * K + k0 + ac];
        }
        #pragma unroll
        for (int ks = 0; ks < 4; ks++) {
            int k0 = ks << 3;
            unsigned afr[2][4], bfr[4][2];
            #pragma unroll
            for (int mt = 0; mt < 2; mt++) {
                int rb = wm + (mt << 4) + gq;
                afr[mt][0] = f2tf32(As[rb    ][k0 + tg    ]);
                afr[mt][1] = f2tf32(As[rb + 8][k0 + tg    ]);
                afr[mt][2] = f2tf32(As[rb    ][k0 + tg + 4]);
                afr[mt][3] = f2tf32(As[rb + 8][k0 + tg + 4]);
            }
            #pragma unroll
            for (int nt = 0; nt < 4; nt++) {
                int nb = wn + (nt << 3) + gq;
                bfr[nt][0] = f2tf32(Bs[nb][k0 + tg    ]);
                bfr[nt][1] = f2tf32(Bs[nb][k0 + tg + 4]);
            }
            #pragma unroll
            for (int mt = 0; mt < 2; mt++)
                #pragma unroll
                for (int nt = 0; nt < 4; nt++)
                    mma_tf32(acc[mt][nt], afr[mt], bfr[nt]);
        }
        __syncthreads();
    }

    // Epilogue: c-frag (row = gq / gq+8, col = 2*tg, 2*tg+1)
    #pragma unroll
    for (int mt = 0; mt < 2; mt++) {
        #pragma unroll
        for (int rr = 0; rr < 2; rr++) {
            int m = m0 + wm + (mt << 4) + gq + (rr << 3);
            // MODE 1 scatter coords (per row)
            int b_ = 0, h_ = 0, w_ = 0;
            if constexpr (MODE == 1) {
                int win = m >> 6, n = m & 63;
                b_ = win >> 8;
                int wi = win & 255;
                h_ = ((((wi >> 4) << 3) + (n >> 3)) + 4) & 127;
                w_ = ((((wi & 15) << 3) + (n & 7)) + 4) & 127;
            }
            #pragma unroll
            for (int nt = 0; nt < 4; nt++) {
                int o = o0 + wn + (nt << 3) + (tg << 1);
                float v0 = acc[mt][nt][(rr << 1)];
                float v1 = acc[mt][nt][(rr << 1) + 1];
                if constexpr (MODE == 0) {
                    if (o < 192) { v0 += bias[o]; v1 += bias[o + 1]; }
                    else if (o >= 384) { v0 += bias2[o - 384]; v1 += bias2[o - 383]; }
                    *(float2*)&g_qkv[(size_t)m * 576 + o] = make_float2(v0, v1);
                } else if constexpr (MODE == 1) {
                    v0 += bias[o];
                    v1 += bias[o + 1];
                    size_t hw = (size_t)(h_ << 7) + w_;
                    v0 += aux[(((size_t)b_ * CCH + o) << 14) + hw];
                    v1 += aux[(((size_t)b_ * CCH + o + 1) << 14) + hw];
                    *(float2*)&g_x1[(size_t)((b_ << 14) + hw) * CCH + o] = make_float2(v0, v1);
                } else if constexpr (MODE == 2) {
                    v0 += bias[o];
                    v1 += bias[o + 1];
                    v0 = 0.5f * v0 * (1.0f + erff(v0 * 0.70710678118654752f));
                    v1 = 0.5f * v1 * (1.0f + erff(v1 * 0.70710678118654752f));
                    *(float2*)&g_h[(size_t)m * HID + o] = make_float2(v0, v1);
                } else {
                    const float* x1r = g_x1 + (size_t)m * CCH;
                    v0 += bias[o] + x1r[o];
                    v1 += bias[o + 1] + x1r[o + 1];
                    int b = m >> 14, hw = m & 16383;
                    outext[(((size_t)b * CCH + o) << 14) + hw] = v0;
                    outext[(((size_t)b * CCH + o + 1) << 14) + hw] = v1;
                }
            }
        }
    }
}

// ---------------------------------------------------------------------------
extern "C" void kernel_launch(void* const* d_in, const int* in_sizes, int n_in,
                              void* d_out, int out_size) {
    const float* x        = (const float*)d_in[0];
    const float* norm1_w  = (const float*)d_in[1];
    const float* norm1_b  = (const float*)d_in[2];
    const float* qkv_w    = (const float*)d_in[3];
    const float* q_bias   = (const float*)d_in[4];
    const float* v_bias   = (const float*)d_in[5];
    const float* logit_sc = (const float*)d_in[6];
    const float* cpb_w1   = (const float*)d_in[7];
    const float* cpb_b1   = (const float*)d_in[8];
    const float* cpb_w2   = (const float*)d_in[9];
    const float* proj_w   = (const float*)d_in[10];
    const float* proj_b   = (const float*)d_in[11];
    const float* norm2_w  = (const float*)d_in[12];
    const float* norm2_b  = (const float*)d_in[13];
    const float* fc1_w    = (const float*)d_in[14];
    const float* fc1_b    = (const float*)d_in[15];
    const float* fc2_w    = (const float*)d_in[16];
    const float* fc2_b    = (const float*)d_in[17];
    float* out = (float*)d_out;

    cpb_table_kernel<<<225, 512>>>(cpb_w1, cpb_b1, cpb_w2);
    rpbias_kernel<<<96, 256>>>();
    ln1_kernel<<<TOK / 32, 192>>>(x, norm1_w, norm1_b);
    gemm_kernel<0><<<dim3(9, TOK / 128), 256>>>(qkv_w, q_bias, v_bias, nullptr, nullptr);
    attn_kernel<<<dim3(HEADS, NWIN), 128>>>(logit_sc);
    gemm_kernel<1><<<dim3(3, TOK / 128), 256>>>(proj_w, proj_b, nullptr, x, nullptr);
    ln2_kernel<<<TOK / 8, 256>>>(norm2_w, norm2_b);
    gemm_kernel<2><<<dim3(12, TOK / 128), 256>>>(fc1_w, fc1_b, nullptr, nullptr, nullptr);
    gemm_kernel<3><<<dim3(3, TOK / 128), 256>>>(fc2_w, fc2_b, nullptr, nullptr, out);
}

// round 6
// speedup vs baseline: 1.3028x; 1.3028x over previous
#include <cuda_runtime.h>
#include <cuda_bf16.h>
#include <math.h>

// ---------------------------------------------------------------------------
// SwinV2 block. Round 5: GEMMs on bf16 mma.m16n8k16 + ldmatrix fragments.
// B=8, C=192, H=W=128, HEADS=6, WS=8, SHIFT=4, N=64, HIDDEN=768
// ---------------------------------------------------------------------------

#define TOK   131072
#define CCH   192
#define HEADS 6
#define HDIM  32
#define NWIN  2048
#define HID   768

__device__ float g_xw  [ (size_t)TOK * CCH ];
__device__ float g_qkv [ (size_t)TOK * 576 ];
__device__ float g_ao  [ (size_t)TOK * CCH ];
__device__ float g_x1  [ (size_t)TOK * CCH ];
__device__ float g_h   [ (size_t)TOK * HID ];
__device__ float g_table [ 225 * HEADS ];
__device__ float g_rpbias[ HEADS * 64 * 64 ];

// ---------------------------------------------------------------------------
__device__ __forceinline__ float relcoord(int ci) {
    float v = (float)(ci - 7) * (8.0f / 7.0f);
    float r = log2f(fabsf(v) + 1.0f) * (1.0f / 3.0f);
    return (v < 0.0f) ? -r : r;
}

__global__ void cpb_table_kernel(const float* __restrict__ w1,
                                 const float* __restrict__ b1,
                                 const float* __restrict__ w2) {
    __shared__ float hid[512];
    int pos = blockIdx.x;
    int a = pos / 15, b = pos % 15;
    float r0 = relcoord(a), r1 = relcoord(b);
    int u = threadIdx.x;
    hid[u] = fmaxf(0.0f, r0 * w1[2 * u] + r1 * w1[2 * u + 1] + b1[u]);
    __syncthreads();
    int warp = u >> 5, lane = u & 31;
    if (warp < HEADS) {
        float s = 0.0f;
        #pragma unroll
        for (int k = 0; k < 16; k++) {
            int uu = lane + (k << 5);
            s += hid[uu] * w2[warp * 512 + uu];
        }
        #pragma unroll
        for (int off = 16; off > 0; off >>= 1)
            s += __shfl_xor_sync(0xffffffffu, s, off);
        if (lane == 0) g_table[pos * HEADS + warp] = s;
    }
}

__global__ void rpbias_kernel() {
    int e = blockIdx.x * blockDim.x + threadIdx.x;
    int h = e >> 12;
    int rem = e & 4095;
    int i = rem >> 6, j = rem & 63;
    int d0 = (i >> 3) - (j >> 3) + 7;
    int d1 = (i & 7) - (j & 7) + 7;
    float t = g_table[(d0 * 15 + d1) * HEADS + h];
    g_rpbias[e] = 16.0f / (1.0f + expf(-t));
}

// ---------------------------------------------------------------------------
__global__ void ln1_kernel(const float* __restrict__ x,
                           const float* __restrict__ nw,
                           const float* __restrict__ nb) {
    __shared__ float s[32][193];
    __shared__ float smu[32], srs[32];
    int tid = threadIdx.x;
    int t0 = blockIdx.x << 5;

    for (int e = tid; e < 32 * 192; e += 192) {
        int tk = e & 31;
        int c  = e >> 5;
        int t  = t0 + tk;
        int win = t >> 6, n = t & 63;
        int b = win >> 8, wi = win & 255;
        int h = ((((wi >> 4) << 3) + (n >> 3)) + 4) & 127;
        int w = ((((wi & 15) << 3) + (n & 7)) + 4) & 127;
        s[tk][c] = x[(((size_t)b * CCH + c) << 14) + (h << 7) + w];
    }
    __syncthreads();
    if (tid < 32) {
        float sum = 0.0f, sq = 0.0f;
        #pragma unroll 4
        for (int c = 0; c < 192; c++) { float v = s[tid][c]; sum += v; sq += v * v; }
        float mu = sum * (1.0f / 192.0f);
        float var = sq * (1.0f / 192.0f) - mu * mu;
        smu[tid] = mu;
        srs[tid] = rsqrtf(var + 1e-5f);
    }
    __syncthreads();
    int c = tid;
    float wv = nw[c], bv = nb[c];
    #pragma unroll 4
    for (int tk = 0; tk < 32; tk++) {
        g_xw[(size_t)(t0 + tk) * CCH + c] = (s[tk][c] - smu[tk]) * srs[tk] * wv + bv;
    }
}

__global__ void ln2_kernel(const float* __restrict__ nw,
                           const float* __restrict__ nb) {
    int warp = threadIdx.x >> 5, lane = threadIdx.x & 31;
    int p = (blockIdx.x << 3) + warp;
    const float* row = g_x1 + (size_t)p * CCH;
    float v[6];
    float sum = 0.0f, sq = 0.0f;
    #pragma unroll
    for (int k = 0; k < 6; k++) {
        v[k] = row[lane + (k << 5)];
        sum += v[k]; sq += v[k] * v[k];
    }
    #pragma unroll
    for (int off = 16; off > 0; off >>= 1) {
        sum += __shfl_xor_sync(0xffffffffu, sum, off);
        sq  += __shfl_xor_sync(0xffffffffu, sq,  off);
    }
    float mu = sum * (1.0f / 192.0f);
    float rstd = rsqrtf(sq * (1.0f / 192.0f) - mu * mu + 1e-5f);
    float* out = g_xw + (size_t)p * CCH;
    #pragma unroll
    for (int k = 0; k < 6; k++) {
        int c = lane + (k << 5);
        out[c] = (v[k] - mu) * rstd * nw[c] + nb[c];
    }
}

// ---------------------------------------------------------------------------
__device__ __forceinline__ int swin_region(int v) {
    return (v < 120) ? 0 : ((v < 124) ? 1 : 2);
}

__global__ void attn_kernel(const float* __restrict__ logit_scale) {
    __shared__ __align__(16) float sq[64][36];
    __shared__ __align__(16) float sk[64][36];
    __shared__ __align__(16) float sv[64][36];
    __shared__ float sS[64][65];
    __shared__ int sreg[64];

    int head = blockIdx.x;
    int wg   = blockIdx.y;
    int tid  = threadIdx.x;
    int t0   = wg << 6;
    int wi   = wg & 255;
    int wh   = wi >> 4, ww = wi & 15;

    for (int e = tid; e < 2048; e += 128) {
        int n = e >> 5, d = e & 31;
        size_t g = (size_t)(t0 + n) * 576 + (head << 5) + d;
        sq[n][d] = g_qkv[g];
        sk[n][d] = g_qkv[g + 192];
        sv[n][d] = g_qkv[g + 384];
    }
    __syncthreads();

    float ls = expf(fminf(logit_scale[head], 4.6051701859880914f));

    if (tid < 64) {
        int r = tid;
        float s = 0.0f;
        #pragma unroll
        for (int d = 0; d < 32; d++) s += sq[r][d] * sq[r][d];
        float sc = ls / fmaxf(sqrtf(s), 1e-12f);
        #pragma unroll
        for (int d = 0; d < 32; d++) sq[r][d] *= sc;
        int hs = (wh << 3) + (r >> 3);
        int ws_ = (ww << 3) + (r & 7);
        sreg[r] = 3 * swin_region(hs) + swin_region(ws_);
    } else {
        int r = tid - 64;
        float s = 0.0f;
        #pragma unroll
        for (int d = 0; d < 32; d++) s += sk[r][d] * sk[r][d];
        float sc = 1.0f / fmaxf(sqrtf(s), 1e-12f);
        #pragma unroll
        for (int d = 0; d < 32; d++) sk[r][d] *= sc;
    }
    __syncthreads();

    #pragma unroll 1
    for (int it = 0; it < 32; it++) {
        int s = tid + (it << 7);
        int i = s >> 6, j = s & 63;
        const float4* qv = (const float4*)sq[i];
        const float4* kv = (const float4*)sk[j];
        float acc = 0.0f;
        #pragma unroll
        for (int d = 0; d < 8; d++) {
            float4 a = qv[d], b = kv[d];
            acc += a.x * b.x + a.y * b.y + a.z * b.z + a.w * b.w;
        }
        acc += g_rpbias[(head << 12) + (i << 6) + j];
        if (sreg[i] != sreg[j]) acc -= 100.0f;
        sS[i][j] = acc;
    }
    __syncthreads();

    if (tid < 64) {
        int r = tid;
        float m = -1e30f;
        #pragma unroll 4
        for (int j = 0; j < 64; j++) m = fmaxf(m, sS[r][j]);
        float sum = 0.0f;
        #pragma unroll 4
        for (int j = 0; j < 64; j++) { float e = expf(sS[r][j] - m); sS[r][j] = e; sum += e; }
        float inv = 1.0f / sum;
        #pragma unroll 4
        for (int j = 0; j < 64; j++) sS[r][j] *= inv;
    }
    __syncthreads();

    #pragma unroll 1
    for (int it = 0; it < 16; it++) {
        int e = tid + (it << 7);
        int i = e >> 5, d = e & 31;
        float acc = 0.0f;
        #pragma unroll
        for (int j = 0; j < 64; j++) acc += sS[i][j] * sv[j][d];
        g_ao[(size_t)(t0 + i) * CCH + (head << 5) + d] = acc;
    }
}

// ---------------------------------------------------------------------------
// bf16 tensor-core GEMM: out[M x NC] = A[M x K] @ W[NC x K]^T (+ epilogue)
// BM=128, BN=64, BK=32, 256 threads (8 warps 4Mx2N), warp tile 32x32,
// mma.sync.m16n8k16 bf16 (fp32 accum), ldmatrix fragment loads,
// fp32->bf16 conversion fused into the smem staging step.
// ---------------------------------------------------------------------------
__device__ __forceinline__ unsigned smem_u32(const void* p) {
    return (unsigned)__cvta_generic_to_shared(p);
}

__device__ __forceinline__ void ldsm_x4(unsigned& r0, unsigned& r1,
                                        unsigned& r2, unsigned& r3, unsigned addr) {
    asm volatile("ldmatrix.sync.aligned.m8n8.x4.shared.b16 {%0,%1,%2,%3}, [%4];"
                 : "=r"(r0), "=r"(r1), "=r"(r2), "=r"(r3) : "r"(addr));
}

__device__ __forceinline__ void mma_bf16(float* c, const unsigned* a, const unsigned* b) {
    asm volatile(
        "mma.sync.aligned.m16n8k16.row.col.f32.bf16.bf16.f32 "
        "{%0,%1,%2,%3}, {%4,%5,%6,%7}, {%8,%9}, {%0,%1,%2,%3};"
        : "+f"(c[0]), "+f"(c[1]), "+f"(c[2]), "+f"(c[3])
        : "r"(a[0]), "r"(a[1]), "r"(a[2]), "r"(a[3]), "r"(b[0]), "r"(b[1]));
}

template <int MODE>
__global__ void __launch_bounds__(256) gemm_kernel(const float* __restrict__ W,
                                                   const float* __restrict__ bias,
                                                   const float* __restrict__ bias2,
                                                   const float* __restrict__ aux,
                                                   float* __restrict__ outext) {
    constexpr int K  = (MODE == 3) ? 768 : 192;
    constexpr int NK = K >> 5;

    const float* A = (MODE == 0 || MODE == 2) ? g_xw : (MODE == 1 ? g_ao : g_h);

    __shared__ __align__(16) __nv_bfloat16 As[128][40];
    __shared__ __align__(16) __nv_bfloat16 Bs[64][40];

    int tid = threadIdx.x;
    int m0 = blockIdx.y << 7;
    int o0 = blockIdx.x << 6;
    const float* Ab = A + (size_t)m0 * K;
    const float* Wb = W + (size_t)o0 * K;

    int ar = tid >> 3;            // 0..31
    int ac = (tid & 7) << 2;      // 0,4,...,28

    float4 pa[4], pb[2];
    #pragma unroll
    for (int p = 0; p < 4; p++)
        pa[p] = *(const float4*)&Ab[(size_t)(ar + (p << 5)) * K + ac];
    #pragma unroll
    for (int p = 0; p < 2; p++)
        pb[p] = *(const float4*)&Wb[(size_t)(ar + (p << 5)) * K + ac];

    int warp = tid >> 5;
    int lane = tid & 31;
    int wm = (warp & 3) << 5;     // warp M offset (4 warps)
    int wn = (warp >> 2) << 5;    // warp N offset (2 warps)
    int gq = lane >> 2;
    int tg = lane & 3;

    // ldmatrix source addresses (bytes), k-chunk 0
    int rowA = lane & 15;
    int colA = (lane >> 4) << 3;
    unsigned aBase[2];
    #pragma unroll
    for (int mt = 0; mt < 2; mt++)
        aBase[mt] = smem_u32(&As[wm + (mt << 4) + rowA][colA]);
    int rowB = (lane & 7) + ((lane >> 4) << 3);
    int colB = ((lane >> 3) & 1) << 3;
    unsigned bBase[2];
    #pragma unroll
    for (int q = 0; q < 2; q++)
        bBase[q] = smem_u32(&Bs[wn + (q << 4) + rowB][colB]);

    float acc[2][4][4];
    #pragma unroll
    for (int mt = 0; mt < 2; mt++)
        #pragma unroll
        for (int nt = 0; nt < 4; nt++)
            #pragma unroll
            for (int r = 0; r < 4; r++) acc[mt][nt][r] = 0.0f;

    #pragma unroll 1
    for (int kt = 0; kt < NK; kt++) {
        #pragma unroll
        for (int p = 0; p < 4; p++) {
            __nv_bfloat162 h0 = __floats2bfloat162_rn(pa[p].x, pa[p].y);
            __nv_bfloat162 h1 = __floats2bfloat162_rn(pa[p].z, pa[p].w);
            *(__nv_bfloat162*)&As[ar + (p << 5)][ac]     = h0;
            *(__nv_bfloat162*)&As[ar + (p << 5)][ac + 2] = h1;
        }
        #pragma unroll
        for (int p = 0; p < 2; p++) {
            __nv_bfloat162 h0 = __floats2bfloat162_rn(pb[p].x, pb[p].y);
            __nv_bfloat162 h1 = __floats2bfloat162_rn(pb[p].z, pb[p].w);
            *(__nv_bfloat162*)&Bs[ar + (p << 5)][ac]     = h0;
            *(__nv_bfloat162*)&Bs[ar + (p << 5)][ac + 2] = h1;
        }
        __syncthreads();
        if (kt + 1 < NK) {
            int k0 = (kt + 1) << 5;
            #pragma unroll
            for (int p = 0; p < 4; p++)
                pa[p] = *(const float4*)&Ab[(size_t)(ar + (p << 5)) * K + k0 + ac];
            #pragma unroll
            for (int p = 0; p < 2; p++)
                pb[p] = *(const float4*)&Wb[(size_t)(ar + (p << 5)) * K + k0 + ac];
        }
        #pragma unroll
        for (int ks = 0; ks < 2; ks++) {
            unsigned af[2][4], bf[2][4];
            #pragma unroll
            for (int mt = 0; mt < 2; mt++)
                ldsm_x4(af[mt][0], af[mt][1], af[mt][2], af[mt][3], aBase[mt] + ks * 32);
            #pragma unroll
            for (int q = 0; q < 2; q++)
                ldsm_x4(bf[q][0], bf[q][1], bf[q][2], bf[q][3], bBase[q] + ks * 32);
            #pragma unroll
            for (int mt = 0; mt < 2; mt++)
                #pragma unroll
                for (int nt = 0; nt < 4; nt++) {
                    unsigned bb[2] = { bf[nt >> 1][(nt & 1) << 1],
                                       bf[nt >> 1][((nt & 1) << 1) + 1] };
                    mma_bf16(acc[mt][nt], af[mt], bb);
                }
        }
        __syncthreads();
    }

    // Epilogue (acc rows: gq / gq+8; cols: 2*tg, 2*tg+1)
    #pragma unroll
    for (int mt = 0; mt < 2; mt++) {
        #pragma unroll
        for (int rr = 0; rr < 2; rr++) {
            int m = m0 + wm + (mt << 4) + gq + (rr << 3);
            int b_ = 0, h_ = 0, w_ = 0;
            if constexpr (MODE == 1) {
                int win = m >> 6, n = m & 63;
                b_ = win >> 8;
                int wi = win & 255;
                h_ = ((((wi >> 4) << 3) + (n >> 3)) + 4) & 127;
                w_ = ((((wi & 15) << 3) + (n & 7)) + 4) & 127;
            }
            #pragma unroll
            for (int nt = 0; nt < 4; nt++) {
                int o = o0 + wn + (nt << 3) + (tg << 1);
                float v0 = acc[mt][nt][(rr << 1)];
                float v1 = acc[mt][nt][(rr << 1) + 1];
                if constexpr (MODE == 0) {
                    if (o < 192) { v0 += bias[o]; v1 += bias[o + 1]; }
                    else if (o >= 384) { v0 += bias2[o - 384]; v1 += bias2[o - 383]; }
                    *(float2*)&g_qkv[(size_t)m * 576 + o] = make_float2(v0, v1);
                } else if constexpr (MODE == 1) {
                    v0 += bias[o];
                    v1 += bias[o + 1];
                    size_t hw = (size_t)(h_ << 7) + w_;
                    v0 += aux[(((size_t)b_ * CCH + o) << 14) + hw];
                    v1 += aux[(((size_t)b_ * CCH + o + 1) << 14) + hw];
                    *(float2*)&g_x1[(size_t)((b_ << 14) + hw) * CCH + o] = make_float2(v0, v1);
                } else if constexpr (MODE == 2) {
                    v0 += bias[o];
                    v1 += bias[o + 1];
                    v0 = 0.5f * v0 * (1.0f + erff(v0 * 0.70710678118654752f));
                    v1 = 0.5f * v1 * (1.0f + erff(v1 * 0.70710678118654752f));
                    *(float2*)&g_h[(size_t)m * HID + o] = make_float2(v0, v1);
                } else {
                    const float* x1r = g_x1 + (size_t)m * CCH;
                    v0 += bias[o] + x1r[o];
                    v1 += bias[o + 1] + x1r[o + 1];
                    int b = m >> 14, hw = m & 16383;
                    outext[(((size_t)b * CCH + o) << 14) + hw] = v0;
                    outext[(((size_t)b * CCH + o + 1) << 14) + hw] = v1;
                }
            }
        }
    }
}

// ---------------------------------------------------------------------------
extern "C" void kernel_launch(void* const* d_in, const int* in_sizes, int n_in,
                              void* d_out, int out_size) {
    const float* x        = (const float*)d_in[0];
    const float* norm1_w  = (const float*)d_in[1];
    const float* norm1_b  = (const float*)d_in[2];
    const float* qkv_w    = (const float*)d_in[3];
    const float* q_bias   = (const float*)d_in[4];
    const float* v_bias   = (const float*)d_in[5];
    const float* logit_sc = (const float*)d_in[6];
    const float* cpb_w1   = (const float*)d_in[7];
    const float* cpb_b1   = (const float*)d_in[8];
    const float* cpb_w2   = (const float*)d_in[9];
    const float* proj_w   = (const float*)d_in[10];
    const float* proj_b   = (const float*)d_in[11];
    const float* norm2_w  = (const float*)d_in[12];
    const float* norm2_b  = (const float*)d_in[13];
    const float* fc1_w    = (const float*)d_in[14];
    const float* fc1_b    = (const float*)d_in[15];
    const float* fc2_w    = (const float*)d_in[16];
    const float* fc2_b    = (const float*)d_in[17];
    float* out = (float*)d_out;

    cpb_table_kernel<<<225, 512>>>(cpb_w1, cpb_b1, cpb_w2);
    rpbias_kernel<<<96, 256>>>();
    ln1_kernel<<<TOK / 32, 192>>>(x, norm1_w, norm1_b);
    gemm_kernel<0><<<dim3(9, TOK / 128), 256>>>(qkv_w, q_bias, v_bias, nullptr, nullptr);
    attn_kernel<<<dim3(HEADS, NWIN), 128>>>(logit_sc);
    gemm_kernel<1><<<dim3(3, TOK / 128), 256>>>(proj_w, proj_b, nullptr, x, nullptr);
    ln2_kernel<<<TOK / 8, 256>>>(norm2_w, norm2_b);
    gemm_kernel<2><<<dim3(12, TOK / 128), 256>>>(fc1_w, fc1_b, nullptr, nullptr, nullptr);
    gemm_kernel<3><<<dim3(3, TOK / 128), 256>>>(fc2_w, fc2_b, nullptr, nullptr, out);
}

// round 7
// speedup vs baseline: 1.4683x; 1.1270x over previous
#include <cuda_runtime.h>
#include <cuda_bf16.h>
#include <math.h>

// ---------------------------------------------------------------------------
// SwinV2 block. Round 6: all-bf16 GEMM dataflow, cp.async double-buffered
// staging, BM=256 / warp-tile 64x32 bf16 mma.m16n8k16.
// B=8, C=192, H=W=128, HEADS=6, WS=8, SHIFT=4, N=64, HIDDEN=768
// ---------------------------------------------------------------------------

#define TOK   131072
#define CCH   192
#define HEADS 6
#define NWIN  2048
#define HID   768

typedef __nv_bfloat16 bf16;
typedef __nv_bfloat162 bf162;

// activations (bf16) + residual (fp32) scratch
__device__ bf16  g_xwb [ (size_t)TOK * CCH ];    // LN1 / LN2 output
__device__ bf16  g_qkvb[ (size_t)TOK * 576 ];
__device__ bf16  g_aob [ (size_t)TOK * CCH ];
__device__ float g_x1  [ (size_t)TOK * CCH ];
__device__ bf16  g_hb  [ (size_t)TOK * HID ];
// bf16 weights
__device__ bf16  g_wqkv[ 576 * 192 ];
__device__ bf16  g_wproj[ 192 * 192 ];
__device__ bf16  g_wfc1[ 768 * 192 ];
__device__ bf16  g_wfc2[ 192 * 768 ];
// CPB
__device__ float g_table [ 225 * HEADS ];
__device__ float g_rpbias[ HEADS * 64 * 64 ];

// ---------------------------------------------------------------------------
__global__ void cvt_w_kernel(const float* __restrict__ src, bf16* __restrict__ dst) {
    int i = (blockIdx.x * 256 + threadIdx.x) << 2;
    float4 v = *(const float4*)(src + i);
    bf162 h0 = __floats2bfloat162_rn(v.x, v.y);
    bf162 h1 = __floats2bfloat162_rn(v.z, v.w);
    *(bf162*)(dst + i)     = h0;
    *(bf162*)(dst + i + 2) = h1;
}

// ---------------------------------------------------------------------------
__device__ __forceinline__ float relcoord(int ci) {
    float v = (float)(ci - 7) * (8.0f / 7.0f);
    float r = log2f(fabsf(v) + 1.0f) * (1.0f / 3.0f);
    return (v < 0.0f) ? -r : r;
}

__global__ void cpb_table_kernel(const float* __restrict__ w1,
                                 const float* __restrict__ b1,
                                 const float* __restrict__ w2) {
    __shared__ float hid[512];
    int pos = blockIdx.x;
    int a = pos / 15, b = pos % 15;
    float r0 = relcoord(a), r1 = relcoord(b);
    int u = threadIdx.x;
    hid[u] = fmaxf(0.0f, r0 * w1[2 * u] + r1 * w1[2 * u + 1] + b1[u]);
    __syncthreads();
    int warp = u >> 5, lane = u & 31;
    if (warp < HEADS) {
        float s = 0.0f;
        #pragma unroll
        for (int k = 0; k < 16; k++) {
            int uu = lane + (k << 5);
            s += hid[uu] * w2[warp * 512 + uu];
        }
        #pragma unroll
        for (int off = 16; off > 0; off >>= 1)
            s += __shfl_xor_sync(0xffffffffu, s, off);
        if (lane == 0) g_table[pos * HEADS + warp] = s;
    }
}

__global__ void rpbias_kernel() {
    int e = blockIdx.x * blockDim.x + threadIdx.x;
    int h = e >> 12;
    int rem = e & 4095;
    int i = rem >> 6, j = rem & 63;
    int d0 = (i >> 3) - (j >> 3) + 7;
    int d1 = (i & 7) - (j & 7) + 7;
    float t = g_table[(d0 * 15 + d1) * HEADS + h];
    g_rpbias[e] = 16.0f / (1.0f + expf(-t));
}

// ---------------------------------------------------------------------------
__global__ void ln1_kernel(const float* __restrict__ x,
                           const float* __restrict__ nw,
                           const float* __restrict__ nb) {
    __shared__ float s[32][193];
    __shared__ float smu[32], srs[32];
    int tid = threadIdx.x;
    int t0 = blockIdx.x << 5;

    for (int e = tid; e < 32 * 192; e += 192) {
        int tk = e & 31;
        int c  = e >> 5;
        int t  = t0 + tk;
        int win = t >> 6, n = t & 63;
        int b = win >> 8, wi = win & 255;
        int h = ((((wi >> 4) << 3) + (n >> 3)) + 4) & 127;
        int w = ((((wi & 15) << 3) + (n & 7)) + 4) & 127;
        s[tk][c] = x[(((size_t)b * CCH + c) << 14) + (h << 7) + w];
    }
    __syncthreads();
    if (tid < 32) {
        float sum = 0.0f, sq = 0.0f;
        #pragma unroll 4
        for (int c = 0; c < 192; c++) { float v = s[tid][c]; sum += v; sq += v * v; }
        float mu = sum * (1.0f / 192.0f);
        float var = sq * (1.0f / 192.0f) - mu * mu;
        smu[tid] = mu;
        srs[tid] = rsqrtf(var + 1e-5f);
    }
    __syncthreads();
    int c = tid;
    float wv = nw[c], bv = nb[c];
    #pragma unroll 4
    for (int tk = 0; tk < 32; tk++) {
        g_xwb[(size_t)(t0 + tk) * CCH + c] =
            __float2bfloat16((s[tk][c] - smu[tk]) * srs[tk] * wv + bv);
    }
}

__global__ void ln2_kernel(const float* __restrict__ nw,
                           const float* __restrict__ nb) {
    int warp = threadIdx.x >> 5, lane = threadIdx.x & 31;
    int p = (blockIdx.x << 3) + warp;
    const float* row = g_x1 + (size_t)p * CCH;
    float v[6];
    float sum = 0.0f, sq = 0.0f;
    #pragma unroll
    for (int k = 0; k < 6; k++) {
        v[k] = row[lane + (k << 5)];
        sum += v[k]; sq += v[k] * v[k];
    }
    #pragma unroll
    for (int off = 16; off > 0; off >>= 1) {
        sum += __shfl_xor_sync(0xffffffffu, sum, off);
        sq  += __shfl_xor_sync(0xffffffffu, sq,  off);
    }
    float mu = sum * (1.0f / 192.0f);
    float rstd = rsqrtf(sq * (1.0f / 192.0f) - mu * mu + 1e-5f);
    bf16* out = g_xwb + (size_t)p * CCH;
    #pragma unroll
    for (int k = 0; k < 6; k++) {
        int c = lane + (k << 5);
        out[c] = __float2bfloat16((v[k] - mu) * rstd * nw[c] + nb[c]);
    }
}

// ---------------------------------------------------------------------------
__device__ __forceinline__ int swin_region(int v) {
    return (v < 120) ? 0 : ((v < 124) ? 1 : 2);
}

__global__ void attn_kernel(const float* __restrict__ logit_scale) {
    __shared__ __align__(16) float sq[64][36];
    __shared__ __align__(16) float sk[64][36];
    __shared__ __align__(16) float sv[64][36];
    __shared__ float sS[64][65];
    __shared__ int sreg[64];

    int head = blockIdx.x;
    int wg   = blockIdx.y;
    int tid  = threadIdx.x;
    int t0   = wg << 6;
    int wi   = wg & 255;
    int wh   = wi >> 4, ww = wi & 15;

    for (int e = tid; e < 1024; e += 128) {
        int n = e >> 4, d2 = (e & 15) << 1;
        const bf16* g = g_qkvb + (size_t)(t0 + n) * 576 + (head << 5) + d2;
        float2 q2 = __bfloat1622float2(*(const bf162*)g);
        float2 k2 = __bfloat1622float2(*(const bf162*)(g + 192));
        float2 v2 = __bfloat1622float2(*(const bf162*)(g + 384));
        sq[n][d2] = q2.x; sq[n][d2 + 1] = q2.y;
        sk[n][d2] = k2.x; sk[n][d2 + 1] = k2.y;
        sv[n][d2] = v2.x; sv[n][d2 + 1] = v2.y;
    }
    __syncthreads();

    float ls = expf(fminf(logit_scale[head], 4.6051701859880914f));

    if (tid < 64) {
        int r = tid;
        float s = 0.0f;
        #pragma unroll
        for (int d = 0; d < 32; d++) s += sq[r][d] * sq[r][d];
        float sc = ls / fmaxf(sqrtf(s), 1e-12f);
        #pragma unroll
        for (int d = 0; d < 32; d++) sq[r][d] *= sc;
        int hs = (wh << 3) + (r >> 3);
        int ws_ = (ww << 3) + (r & 7);
        sreg[r] = 3 * swin_region(hs) + swin_region(ws_);
    } else {
        int r = tid - 64;
        float s = 0.0f;
        #pragma unroll
        for (int d = 0; d < 32; d++) s += sk[r][d] * sk[r][d];
        float sc = 1.0f / fmaxf(sqrtf(s), 1e-12f);
        #pragma unroll
        for (int d = 0; d < 32; d++) sk[r][d] *= sc;
    }
    __syncthreads();

    #pragma unroll 1
    for (int it = 0; it < 32; it++) {
        int s = tid + (it << 7);
        int i = s >> 6, j = s & 63;
        const float4* qv = (const float4*)sq[i];
        const float4* kv = (const float4*)sk[j];
        float acc = 0.0f;
        #pragma unroll
        for (int d = 0; d < 8; d++) {
            float4 a = qv[d], b = kv[d];
            acc += a.x * b.x + a.y * b.y + a.z * b.z + a.w * b.w;
        }
        acc += g_rpbias[(head << 12) + (i << 6) + j];
        if (sreg[i] != sreg[j]) acc -= 100.0f;
        sS[i][j] = acc;
    }
    __syncthreads();

    if (tid < 64) {
        int r = tid;
        float m = -1e30f;
        #pragma unroll 4
        for (int j = 0; j < 64; j++) m = fmaxf(m, sS[r][j]);
        float sum = 0.0f;
        #pragma unroll 4
        for (int j = 0; j < 64; j++) { float e = expf(sS[r][j] - m); sS[r][j] = e; sum += e; }
        float inv = 1.0f / sum;
        #pragma unroll 4
        for (int j = 0; j < 64; j++) sS[r][j] *= inv;
    }
    __syncthreads();

    #pragma unroll 1
    for (int it = 0; it < 16; it++) {
        int e = tid + (it << 7);
        int i = e >> 5, d = e & 31;
        float acc = 0.0f;
        #pragma unroll
        for (int j = 0; j < 64; j++) acc += sS[i][j] * sv[j][d];
        g_aob[(size_t)(t0 + i) * CCH + (head << 5) + d] = __float2bfloat16(acc);
    }
}

// ---------------------------------------------------------------------------
// bf16 tensor-core GEMM: out[M x NC] = A[M x K] @ W[NC x K]^T (+ epilogue)
// BM=256, BN=64, BK=32, 256 threads (8 warps 4Mx2N), warp tile 64x32,
// cp.async 2-stage pipeline, ldmatrix fragments, mma.m16n8k16 bf16.
// ---------------------------------------------------------------------------
__device__ __forceinline__ unsigned smem_u32(const void* p) {
    return (unsigned)__cvta_generic_to_shared(p);
}

__device__ __forceinline__ void cp16(unsigned dst, const void* src) {
    asm volatile("cp.async.cg.shared.global [%0], [%1], 16;" :: "r"(dst), "l"(src));
}

__device__ __forceinline__ void cp_commit() {
    asm volatile("cp.async.commit_group;");
}

template <int N>
__device__ __forceinline__ void cp_wait() {
    asm volatile("cp.async.wait_group %0;" :: "n"(N));
}

__device__ __forceinline__ void ldsm_x4(unsigned& r0, unsigned& r1,
                                        unsigned& r2, unsigned& r3, unsigned addr) {
    asm volatile("ldmatrix.sync.aligned.m8n8.x4.shared.b16 {%0,%1,%2,%3}, [%4];"
                 : "=r"(r0), "=r"(r1), "=r"(r2), "=r"(r3) : "r"(addr));
}

__device__ __forceinline__ void mma_bf16(float* c, const unsigned* a, const unsigned* b) {
    asm volatile(
        "mma.sync.aligned.m16n8k16.row.col.f32.bf16.bf16.f32 "
        "{%0,%1,%2,%3}, {%4,%5,%6,%7}, {%8,%9}, {%0,%1,%2,%3};"
        : "+f"(c[0]), "+f"(c[1]), "+f"(c[2]), "+f"(c[3])
        : "r"(a[0]), "r"(a[1]), "r"(a[2]), "r"(a[3]), "r"(b[0]), "r"(b[1]));
}

template <int MODE>
__global__ void __launch_bounds__(256, 2) gemm_kernel(const bf16* __restrict__ W,
                                                      const float* __restrict__ bias,
                                                      const float* __restrict__ bias2,
                                                      const float* __restrict__ aux,
                                                      float* __restrict__ outext) {
    constexpr int K  = (MODE == 3) ? 768 : 192;
    constexpr int NK = K >> 5;

    const bf16* A = (MODE == 0 || MODE == 2) ? g_xwb : (MODE == 1 ? g_aob : g_hb);

    __shared__ __align__(16) bf16 As[2][256][40];
    __shared__ __align__(16) bf16 Bs[2][64][40];

    int tid = threadIdx.x;
    int m0 = blockIdx.y << 8;
    int o0 = blockIdx.x << 6;
    const bf16* Ab = A + (size_t)m0 * K;
    const bf16* Wb = W + (size_t)o0 * K;

    int lr = tid >> 2;            // 0..63
    int lc = (tid & 3) << 3;      // 0,8,16,24 (elems)

    unsigned asB = smem_u32(&As[0][0][0]);
    unsigned bsB = smem_u32(&Bs[0][0][0]);
    const unsigned AS_BYTES = 256 * 40 * 2;
    const unsigned BS_BYTES = 64 * 40 * 2;

    int warp = tid >> 5;
    int lane = tid & 31;
    int wm = (warp & 3) << 6;     // 4 M-warps, 64 rows each
    int wn = (warp >> 2) << 5;    // 2 N-warps, 32 cols each
    int gq = lane >> 2;
    int tg = lane & 3;

    int rowA = lane & 15;
    int chA  = (lane >> 4);                       // 0/1
    int rowB = (lane & 7) + ((lane >> 4) << 3);
    int chB  = (lane >> 3) & 1;

    float acc[4][4][4];
    #pragma unroll
    for (int mt = 0; mt < 4; mt++)
        #pragma unroll
        for (int nt = 0; nt < 4; nt++)
            #pragma unroll
            for (int r = 0; r < 4; r++) acc[mt][nt][r] = 0.0f;

    // prologue: stage 0
    {
        #pragma unroll
        for (int p = 0; p < 4; p++)
            cp16(asB + ((unsigned)(lr + (p << 6)) * 40 + lc) * 2,
                 Ab + (size_t)(lr + (p << 6)) * K + lc);
        cp16(bsB + ((unsigned)lr * 40 + lc) * 2, Wb + (size_t)lr * K + lc);
        cp_commit();
    }

    #pragma unroll 1
    for (int kt = 0; kt < NK; kt++) {
        int s = kt & 1;
        if (kt + 1 < NK) {
            int sn = (kt + 1) & 1;
            int k0 = (kt + 1) << 5;
            #pragma unroll
            for (int p = 0; p < 4; p++)
                cp16(asB + sn * AS_BYTES + ((unsigned)(lr + (p << 6)) * 40 + lc) * 2,
                     Ab + (size_t)(lr + (p << 6)) * K + k0 + lc);
            cp16(bsB + sn * BS_BYTES + ((unsigned)lr * 40 + lc) * 2,
                 Wb + (size_t)lr * K + k0 + lc);
            cp_commit();
            cp_wait<1>();
        } else {
            cp_wait<0>();
        }
        __syncthreads();

        #pragma unroll
        for (int ks = 0; ks < 2; ks++) {
            unsigned af[4][4], bf[2][4];
            #pragma unroll
            for (int mt = 0; mt < 4; mt++) {
                unsigned addr = asB + s * AS_BYTES +
                    ((unsigned)(wm + (mt << 4) + rowA) * 40 + ((chA + (ks << 1)) << 3)) * 2;
                ldsm_x4(af[mt][0], af[mt][1], af[mt][2], af[mt][3], addr);
            }
            #pragma unroll
            for (int q = 0; q < 2; q++) {
                unsigned addr = bsB + s * BS_BYTES +
                    ((unsigned)(wn + (q << 4) + rowB) * 40 + ((chB + (ks << 1)) << 3)) * 2;
                ldsm_x4(bf[q][0], bf[q][1], bf[q][2], bf[q][3], addr);
            }
            #pragma unroll
            for (int mt = 0; mt < 4; mt++)
                #pragma unroll
                for (int nt = 0; nt < 4; nt++) {
                    unsigned bb[2] = { bf[nt >> 1][(nt & 1) << 1],
                                       bf[nt >> 1][((nt & 1) << 1) + 1] };
                    mma_bf16(acc[mt][nt], af[mt], bb);
                }
        }
        __syncthreads();
    }

    // Epilogue (acc rows: gq / gq+8; cols: 2*tg, 2*tg+1)
    #pragma unroll
    for (int mt = 0; mt < 4; mt++) {
        #pragma unroll
        for (int rr = 0; rr < 2; rr++) {
            int m = m0 + wm + (mt << 4) + gq + (rr << 3);
            int b_ = 0, h_ = 0, w_ = 0;
            if constexpr (MODE == 1) {
                int win = m >> 6, n = m & 63;
                b_ = win >> 8;
                int wi = win & 255;
                h_ = ((((wi >> 4) << 3) + (n >> 3)) + 4) & 127;
                w_ = ((((wi & 15) << 3) + (n & 7)) + 4) & 127;
            }
            #pragma unroll
            for (int nt = 0; nt < 4; nt++) {
                int o = o0 + wn + (nt << 3) + (tg << 1);
                float v0 = acc[mt][nt][(rr << 1)];
                float v1 = acc[mt][nt][(rr << 1) + 1];
                if constexpr (MODE == 0) {
                    if (o < 192) { v0 += bias[o]; v1 += bias[o + 1]; }
                    else if (o >= 384) { v0 += bias2[o - 384]; v1 += bias2[o - 383]; }
                    *(bf162*)&g_qkvb[(size_t)m * 576 + o] = __floats2bfloat162_rn(v0, v1);
                } else if constexpr (MODE == 1) {
                    v0 += bias[o];
                    v1 += bias[o + 1];
                    size_t hw = (size_t)(h_ << 7) + w_;
                    v0 += aux[(((size_t)b_ * CCH + o) << 14) + hw];
                    v1 += aux[(((size_t)b_ * CCH + o + 1) << 14) + hw];
                    *(float2*)&g_x1[(size_t)((b_ << 14) + hw) * CCH + o] = make_float2(v0, v1);
                } else if constexpr (MODE == 2) {
                    v0 += bias[o];
                    v1 += bias[o + 1];
                    v0 = 0.5f * v0 * (1.0f + erff(v0 * 0.70710678118654752f));
                    v1 = 0.5f * v1 * (1.0f + erff(v1 * 0.70710678118654752f));
                    *(bf162*)&g_hb[(size_t)m * HID + o] = __floats2bfloat162_rn(v0, v1);
                } else {
                    const float* x1r = g_x1 + (size_t)m * CCH;
                    v0 += bias[o] + x1r[o];
                    v1 += bias[o + 1] + x1r[o + 1];
                    int b = m >> 14, hw = m & 16383;
                    outext[(((size_t)b * CCH + o) << 14) + hw] = v0;
                    outext[(((size_t)b * CCH + o + 1) << 14) + hw] = v1;
                }
            }
        }
    }
}

// ---------------------------------------------------------------------------
extern "C" void kernel_launch(void* const* d_in, const int* in_sizes, int n_in,
                              void* d_out, int out_size) {
    const float* x        = (const float*)d_in[0];
    const float* norm1_w  = (const float*)d_in[1];
    const float* norm1_b  = (const float*)d_in[2];
    const float* qkv_w    = (const float*)d_in[3];
    const float* q_bias   = (const float*)d_in[4];
    const float* v_bias   = (const float*)d_in[5];
    const float* logit_sc = (const float*)d_in[6];
    const float* cpb_w1   = (const float*)d_in[7];
    const float* cpb_b1   = (const float*)d_in[8];
    const float* cpb_w2   = (const float*)d_in[9];
    const float* proj_w   = (const float*)d_in[10];
    const float* proj_b   = (const float*)d_in[11];
    const float* norm2_w  = (const float*)d_in[12];
    const float* norm2_b  = (const float*)d_in[13];
    const float* fc1_w    = (const float*)d_in[14];
    const float* fc1_b    = (const float*)d_in[15];
    const float* fc2_w    = (const float*)d_in[16];
    const float* fc2_b    = (const float*)d_in[17];
    float* out = (float*)d_out;

    bf16 *wq, *wp, *w1, *w2;
    cudaGetSymbolAddress((void**)&wq, g_wqkv);
    cudaGetSymbolAddress((void**)&wp, g_wproj);
    cudaGetSymbolAddress((void**)&w1, g_wfc1);
    cudaGetSymbolAddress((void**)&w2, g_wfc2);

    cvt_w_kernel<<<108, 256>>>(qkv_w, wq);    // 576*192/1024
    cvt_w_kernel<<<36, 256>>>(proj_w, wp);    // 192*192/1024
    cvt_w_kernel<<<144, 256>>>(fc1_w, w1);    // 768*192/1024
    cvt_w_kernel<<<144, 256>>>(fc2_w, w2);    // 192*768/1024
    cpb_table_kernel<<<225, 512>>>(cpb_w1, cpb_b1, cpb_w2);
    rpbias_kernel<<<96, 256>>>();
    ln1_kernel<<<TOK / 32, 192>>>(x, norm1_w, norm1_b);
    gemm_kernel<0><<<dim3(9, TOK / 256), 256>>>(wq, q_bias, v_bias, nullptr, nullptr);
    attn_kernel<<<dim3(HEADS, NWIN), 128>>>(logit_sc);
    gemm_kernel<1><<<dim3(3, TOK / 256), 256>>>(wp, proj_b, nullptr, x, nullptr);
    ln2_kernel<<<TOK / 8, 256>>>(norm2_w, norm2_b);
    gemm_kernel<2><<<dim3(12, TOK / 256), 256>>>(w1, fc1_b, nullptr, nullptr, nullptr);
    gemm_kernel<3><<<dim3(3, TOK / 256), 256>>>(w2, fc2_b, nullptr, nullptr, out);
}

// round 8
// speedup vs baseline: 1.8197x; 1.2393x over previous
#include <cuda_runtime.h>
#include <cuda_bf16.h>
#include <math.h>

// ---------------------------------------------------------------------------
// SwinV2 block. Round 7: tensor-core attention (bf16 mma for S=QK^T and PV),
// all-bf16 GEMM dataflow with cp.async double buffering.
// B=8, C=192, H=W=128, HEADS=6, WS=8, SHIFT=4, N=64, HIDDEN=768
// ---------------------------------------------------------------------------

#define TOK   131072
#define CCH   192
#define HEADS 6
#define NWIN  2048
#define HID   768

typedef __nv_bfloat16 bf16;
typedef __nv_bfloat162 bf162;

__device__ bf16  g_xwb [ (size_t)TOK * CCH ];
__device__ bf16  g_qkvb[ (size_t)TOK * 576 ];
__device__ bf16  g_aob [ (size_t)TOK * CCH ];
__device__ float g_x1  [ (size_t)TOK * CCH ];
__device__ bf16  g_hb  [ (size_t)TOK * HID ];
__device__ bf16  g_wqkv[ 576 * 192 ];
__device__ bf16  g_wproj[ 192 * 192 ];
__device__ bf16  g_wfc1[ 768 * 192 ];
__device__ bf16  g_wfc2[ 192 * 768 ];
__device__ float g_table [ 225 * HEADS ];
__device__ float g_rpbias[ HEADS * 64 * 64 ];

// ---------------------------------------------------------------------------
__global__ void cvt_w_kernel(const float* __restrict__ src, bf16* __restrict__ dst) {
    int i = (blockIdx.x * 256 + threadIdx.x) << 2;
    float4 v = *(const float4*)(src + i);
    *(bf162*)(dst + i)     = __floats2bfloat162_rn(v.x, v.y);
    *(bf162*)(dst + i + 2) = __floats2bfloat162_rn(v.z, v.w);
}

// ---------------------------------------------------------------------------
__device__ __forceinline__ float relcoord(int ci) {
    float v = (float)(ci - 7) * (8.0f / 7.0f);
    float r = log2f(fabsf(v) + 1.0f) * (1.0f / 3.0f);
    return (v < 0.0f) ? -r : r;
}

__global__ void cpb_table_kernel(const float* __restrict__ w1,
                                 const float* __restrict__ b1,
                                 const float* __restrict__ w2) {
    __shared__ float hid[512];
    int pos = blockIdx.x;
    int a = pos / 15, b = pos % 15;
    float r0 = relcoord(a), r1 = relcoord(b);
    int u = threadIdx.x;
    hid[u] = fmaxf(0.0f, r0 * w1[2 * u] + r1 * w1[2 * u + 1] + b1[u]);
    __syncthreads();
    int warp = u >> 5, lane = u & 31;
    if (warp < HEADS) {
        float s = 0.0f;
        #pragma unroll
        for (int k = 0; k < 16; k++) {
            int uu = lane + (k << 5);
            s += hid[uu] * w2[warp * 512 + uu];
        }
        #pragma unroll
        for (int off = 16; off > 0; off >>= 1)
            s += __shfl_xor_sync(0xffffffffu, s, off);
        if (lane == 0) g_table[pos * HEADS + warp] = s;
    }
}

__global__ void rpbias_kernel() {
    int e = blockIdx.x * blockDim.x + threadIdx.x;
    int h = e >> 12;
    int rem = e & 4095;
    int i = rem >> 6, j = rem & 63;
    int d0 = (i >> 3) - (j >> 3) + 7;
    int d1 = (i & 7) - (j & 7) + 7;
    float t = g_table[(d0 * 15 + d1) * HEADS + h];
    g_rpbias[e] = 16.0f / (1.0f + expf(-t));
}

// ---------------------------------------------------------------------------
__global__ void ln1_kernel(const float* __restrict__ x,
                           const float* __restrict__ nw,
                           const float* __restrict__ nb) {
    __shared__ float s[32][193];
    __shared__ float smu[32], srs[32];
    int tid = threadIdx.x;
    int t0 = blockIdx.x << 5;

    for (int e = tid; e < 32 * 192; e += 192) {
        int tk = e & 31;
        int c  = e >> 5;
        int t  = t0 + tk;
        int win = t >> 6, n = t & 63;
        int b = win >> 8, wi = win & 255;
        int h = ((((wi >> 4) << 3) + (n >> 3)) + 4) & 127;
        int w = ((((wi & 15) << 3) + (n & 7)) + 4) & 127;
        s[tk][c] = x[(((size_t)b * CCH + c) << 14) + (h << 7) + w];
    }
    __syncthreads();
    if (tid < 32) {
        float sum = 0.0f, sq = 0.0f;
        #pragma unroll 4
        for (int c = 0; c < 192; c++) { float v = s[tid][c]; sum += v; sq += v * v; }
        float mu = sum * (1.0f / 192.0f);
        float var = sq * (1.0f / 192.0f) - mu * mu;
        smu[tid] = mu;
        srs[tid] = rsqrtf(var + 1e-5f);
    }
    __syncthreads();
    int c = tid;
    float wv = nw[c], bv = nb[c];
    #pragma unroll 4
    for (int tk = 0; tk < 32; tk++) {
        g_xwb[(size_t)(t0 + tk) * CCH + c] =
            __float2bfloat16((s[tk][c] - smu[tk]) * srs[tk] * wv + bv);
    }
}

__global__ void ln2_kernel(const float* __restrict__ nw,
                           const float* __restrict__ nb) {
    int warp = threadIdx.x >> 5, lane = threadIdx.x & 31;
    int p = (blockIdx.x << 3) + warp;
    const float* row = g_x1 + (size_t)p * CCH;
    float v[6];
    float sum = 0.0f, sq = 0.0f;
    #pragma unroll
    for (int k = 0; k < 6; k++) {
        v[k] = row[lane + (k << 5)];
        sum += v[k]; sq += v[k] * v[k];
    }
    #pragma unroll
    for (int off = 16; off > 0; off >>= 1) {
        sum += __shfl_xor_sync(0xffffffffu, sum, off);
        sq  += __shfl_xor_sync(0xffffffffu, sq,  off);
    }
    float mu = sum * (1.0f / 192.0f);
    float rstd = rsqrtf(sq * (1.0f / 192.0f) - mu * mu + 1e-5f);
    bf16* out = g_xwb + (size_t)p * CCH;
    #pragma unroll
    for (int k = 0; k < 6; k++) {
        int c = lane + (k << 5);
        out[c] = __float2bfloat16((v[k] - mu) * rstd * nw[c] + nb[c]);
    }
}

// ---------------------------------------------------------------------------
__device__ __forceinline__ unsigned smem_u32(const void* p) {
    return (unsigned)__cvta_generic_to_shared(p);
}

__device__ __forceinline__ void ldsm_x4(unsigned& r0, unsigned& r1,
                                        unsigned& r2, unsigned& r3, unsigned addr) {
    asm volatile("ldmatrix.sync.aligned.m8n8.x4.shared.b16 {%0,%1,%2,%3}, [%4];"
                 : "=r"(r0), "=r"(r1), "=r"(r2), "=r"(r3) : "r"(addr));
}

__device__ __forceinline__ void mma_bf16(float* c, const unsigned* a, const unsigned* b) {
    asm volatile(
        "mma.sync.aligned.m16n8k16.row.col.f32.bf16.bf16.f32 "
        "{%0,%1,%2,%3}, {%4,%5,%6,%7}, {%8,%9}, {%0,%1,%2,%3};"
        : "+f"(c[0]), "+f"(c[1]), "+f"(c[2]), "+f"(c[3])
        : "r"(a[0]), "r"(a[1]), "r"(a[2]), "r"(a[3]), "r"(b[0]), "r"(b[1]));
}

// ---------------------------------------------------------------------------
// Tensor-core attention: one block per (head, window), 128 threads (4 warps).
// S = qn kn^T (mma), reg-resident softmax, PV (mma).
// ---------------------------------------------------------------------------
__device__ __forceinline__ int swin_region(int v) {
    return (v < 120) ? 0 : ((v < 124) ? 1 : 2);
}

__global__ void __launch_bounds__(128) attn_kernel(const float* __restrict__ logit_scale) {
    __shared__ __align__(16) bf16 sqb[64][40];
    __shared__ __align__(16) bf16 skb[64][40];
    __shared__ __align__(16) bf16 svT[32][72];
    __shared__ __align__(16) bf16 sP [64][72];
    __shared__ int sreg[64];

    int head = blockIdx.x;
    int wg   = blockIdx.y;
    int tid  = threadIdx.x;
    int t0   = wg << 6;
    int wi   = wg & 255;
    int wh   = wi >> 4, ww = wi & 15;

    float ls = expf(fminf(logit_scale[head], 4.6051701859880914f));

    // V transposed into svT[d][j]
    for (int e = tid; e < 1024; e += 128) {
        int j = e >> 4, d2 = (e & 15) << 1;
        bf162 v = *(const bf162*)(g_qkvb + (size_t)(t0 + j) * 576 + (head << 5) + 384 + d2);
        svT[d2][j]     = v.x;
        svT[d2 + 1][j] = v.y;
    }

    // q/k rows: load, normalize in fp32, store bf16 (ls folded into q)
    {
        int r = tid & 63;
        const bf16* src = g_qkvb + (size_t)(t0 + r) * 576 + (head << 5) + ((tid < 64) ? 0 : 192);
        float v[32];
        float ss = 0.0f;
        #pragma unroll
        for (int i = 0; i < 16; i++) {
            float2 f = __bfloat1622float2(*(const bf162*)(src + (i << 1)));
            v[2 * i] = f.x; v[2 * i + 1] = f.y;
            ss += f.x * f.x + f.y * f.y;
        }
        float sc = ((tid < 64) ? ls : 1.0f) / fmaxf(sqrtf(ss), 1e-12f);
        bf16 (*dst)[40] = (tid < 64) ? sqb : skb;
        #pragma unroll
        for (int i = 0; i < 16; i++)
            *(bf162*)&dst[r][i << 1] = __floats2bfloat162_rn(v[2 * i] * sc, v[2 * i + 1] * sc);
        if (tid < 64) {
            int hs = (wh << 3) + (r >> 3);
            int ws_ = (ww << 3) + (r & 7);
            sreg[r] = 3 * swin_region(hs) + swin_region(ws_);
        }
    }
    __syncthreads();

    int warp = tid >> 5, lane = tid & 31;
    int gq = lane >> 2, tg = lane & 3;
    int rowA = lane & 15, chA = lane >> 4;
    int rowB = (lane & 7) + ((lane >> 4) << 3), chB = (lane >> 3) & 1;

    // S = qn kn^T : warp computes rows 16*warp..+15, all 64 cols
    float acc[8][4];
    #pragma unroll
    for (int nt = 0; nt < 8; nt++)
        #pragma unroll
        for (int r = 0; r < 4; r++) acc[nt][r] = 0.0f;

    #pragma unroll
    for (int ks = 0; ks < 2; ks++) {
        unsigned a[4];
        ldsm_x4(a[0], a[1], a[2], a[3],
                smem_u32(&sqb[(warp << 4) + rowA][(ks << 4) + (chA << 3)]));
        #pragma unroll
        for (int q = 0; q < 4; q++) {
            unsigned b[4];
            ldsm_x4(b[0], b[1], b[2], b[3],
                    smem_u32(&skb[(q << 4) + rowB][(ks << 4) + (chB << 3)]));
            mma_bf16(acc[2 * q],     a, b);
            mma_bf16(acc[2 * q + 1], a, b + 2);
        }
    }

    // bias + mask + softmax in registers
    {
        int r0 = (warp << 4) + gq;
        int r1 = r0 + 8;
        int rg0 = sreg[r0], rg1 = sreg[r1];
        float p0[16], p1[16];
        #pragma unroll
        for (int nt = 0; nt < 8; nt++) {
            int c = (nt << 3) + (tg << 1);
            float2 b0 = *(const float2*)&g_rpbias[(head << 12) + (r0 << 6) + c];
            float2 b1 = *(const float2*)&g_rpbias[(head << 12) + (r1 << 6) + c];
            int cr0 = sreg[c], cr1 = sreg[c + 1];
            p0[2 * nt]     = acc[nt][0] + b0.x + ((rg0 != cr0) ? -100.0f : 0.0f);
            p0[2 * nt + 1] = acc[nt][1] + b0.y + ((rg0 != cr1) ? -100.0f : 0.0f);
            p1[2 * nt]     = acc[nt][2] + b1.x + ((rg1 != cr0) ? -100.0f : 0.0f);
            p1[2 * nt + 1] = acc[nt][3] + b1.y + ((rg1 != cr1) ? -100.0f : 0.0f);
        }
        float m0 = -1e30f, m1 = -1e30f;
        #pragma unroll
        for (int i = 0; i < 16; i++) { m0 = fmaxf(m0, p0[i]); m1 = fmaxf(m1, p1[i]); }
        m0 = fmaxf(m0, __shfl_xor_sync(0xffffffffu, m0, 1));
        m0 = fmaxf(m0, __shfl_xor_sync(0xffffffffu, m0, 2));
        m1 = fmaxf(m1, __shfl_xor_sync(0xffffffffu, m1, 1));
        m1 = fmaxf(m1, __shfl_xor_sync(0xffffffffu, m1, 2));
        float s0 = 0.0f, s1 = 0.0f;
        #pragma unroll
        for (int i = 0; i < 16; i++) {
            p0[i] = __expf(p0[i] - m0); s0 += p0[i];
            p1[i] = __expf(p1[i] - m1); s1 += p1[i];
        }
        s0 += __shfl_xor_sync(0xffffffffu, s0, 1);
        s0 += __shfl_xor_sync(0xffffffffu, s0, 2);
        s1 += __shfl_xor_sync(0xffffffffu, s1, 1);
        s1 += __shfl_xor_sync(0xffffffffu, s1, 2);
        float i0 = 1.0f / s0, i1 = 1.0f / s1;
        #pragma unroll
        for (int nt = 0; nt < 8; nt++) {
            int c = (nt << 3) + (tg << 1);
            *(bf162*)&sP[r0][c] = __floats2bfloat162_rn(p0[2 * nt] * i0, p0[2 * nt + 1] * i0);
            *(bf162*)&sP[r1][c] = __floats2bfloat162_rn(p1[2 * nt] * i1, p1[2 * nt + 1] * i1);
        }
    }
    __syncwarp();

    // O = P V : warp rows 16*warp..+15, 32 dims
    float o[4][4];
    #pragma unroll
    for (int nt = 0; nt < 4; nt++)
        #pragma unroll
        for (int r = 0; r < 4; r++) o[nt][r] = 0.0f;

    #pragma unroll
    for (int ks = 0; ks < 4; ks++) {
        unsigned a[4];
        ldsm_x4(a[0], a[1], a[2], a[3],
                smem_u32(&sP[(warp << 4) + rowA][(ks << 4) + (chA << 3)]));
        #pragma unroll
        for (int q = 0; q < 2; q++) {
            unsigned b[4];
            ldsm_x4(b[0], b[1], b[2], b[3],
                    smem_u32(&svT[(q << 4) + rowB][(ks << 4) + (chB << 3)]));
            mma_bf16(o[2 * q],     a, b);
            mma_bf16(o[2 * q + 1], a, b + 2);
        }
    }

    {
        int r0 = (warp << 4) + gq;
        #pragma unroll
        for (int nt = 0; nt < 4; nt++) {
            int d = (nt << 3) + (tg << 1);
            bf16* dst0 = g_aob + (size_t)(t0 + r0) * CCH + (head << 5) + d;
            bf16* dst1 = dst0 + 8 * CCH;
            *(bf162*)dst0 = __floats2bfloat162_rn(o[nt][0], o[nt][1]);
            *(bf162*)dst1 = __floats2bfloat162_rn(o[nt][2], o[nt][3]);
        }
    }
}

// ---------------------------------------------------------------------------
// bf16 tensor-core GEMM (unchanged from round 6)
// ---------------------------------------------------------------------------
__device__ __forceinline__ void cp16(unsigned dst, const void* src) {
    asm volatile("cp.async.cg.shared.global [%0], [%1], 16;" :: "r"(dst), "l"(src));
}
__device__ __forceinline__ void cp_commit() {
    asm volatile("cp.async.commit_group;");
}
template <int N>
__device__ __forceinline__ void cp_wait() {
    asm volatile("cp.async.wait_group %0;" :: "n"(N));
}

template <int MODE>
__global__ void __launch_bounds__(256, 2) gemm_kernel(const bf16* __restrict__ W,
                                                      const float* __restrict__ bias,
                                                      const float* __restrict__ bias2,
                                                      const float* __restrict__ aux,
                                                      float* __restrict__ outext) {
    constexpr int K  = (MODE == 3) ? 768 : 192;
    constexpr int NK = K >> 5;

    const bf16* A = (MODE == 0 || MODE == 2) ? g_xwb : (MODE == 1 ? g_aob : g_hb);

    __shared__ __align__(16) bf16 As[2][256][40];
    __shared__ __align__(16) bf16 Bs[2][64][40];

    int tid = threadIdx.x;
    int m0 = blockIdx.y << 8;
    int o0 = blockIdx.x << 6;
    const bf16* Ab = A + (size_t)m0 * K;
    const bf16* Wb = W + (size_t)o0 * K;

    int lr = tid >> 2;
    int lc = (tid & 3) << 3;

    unsigned asB = smem_u32(&As[0][0][0]);
    unsigned bsB = smem_u32(&Bs[0][0][0]);
    const unsigned AS_BYTES = 256 * 40 * 2;
    const unsigned BS_BYTES = 64 * 40 * 2;

    int warp = tid >> 5;
    int lane = tid & 31;
    int wm = (warp & 3) << 6;
    int wn = (warp >> 2) << 5;
    int gq = lane >> 2;
    int tg = lane & 3;

    int rowA = lane & 15;
    int chA  = (lane >> 4);
    int rowB = (lane & 7) + ((lane >> 4) << 3);
    int chB  = (lane >> 3) & 1;

    float acc[4][4][4];
    #pragma unroll
    for (int mt = 0; mt < 4; mt++)
        #pragma unroll
        for (int nt = 0; nt < 4; nt++)
            #pragma unroll
            for (int r = 0; r < 4; r++) acc[mt][nt][r] = 0.0f;

    {
        #pragma unroll
        for (int p = 0; p < 4; p++)
            cp16(asB + ((unsigned)(lr + (p << 6)) * 40 + lc) * 2,
                 Ab + (size_t)(lr + (p << 6)) * K + lc);
        cp16(bsB + ((unsigned)lr * 40 + lc) * 2, Wb + (size_t)lr * K + lc);
        cp_commit();
    }

    #pragma unroll 1
    for (int kt = 0; kt < NK; kt++) {
        int s = kt & 1;
        if (kt + 1 < NK) {
            int sn = (kt + 1) & 1;
            int k0 = (kt + 1) << 5;
            #pragma unroll
            for (int p = 0; p < 4; p++)
                cp16(asB + sn * AS_BYTES + ((unsigned)(lr + (p << 6)) * 40 + lc) * 2,
                     Ab + (size_t)(lr + (p << 6)) * K + k0 + lc);
            cp16(bsB + sn * BS_BYTES + ((unsigned)lr * 40 + lc) * 2,
                 Wb + (size_t)lr * K + k0 + lc);
            cp_commit();
            cp_wait<1>();
        } else {
            cp_wait<0>();
        }
        __syncthreads();

        #pragma unroll
        for (int ks = 0; ks < 2; ks++) {
            unsigned af[4][4], bf[2][4];
            #pragma unroll
            for (int mt = 0; mt < 4; mt++) {
                unsigned addr = asB + s * AS_BYTES +
                    ((unsigned)(wm + (mt << 4) + rowA) * 40 + ((chA + (ks << 1)) << 3)) * 2;
                ldsm_x4(af[mt][0], af[mt][1], af[mt][2], af[mt][3], addr);
            }
            #pragma unroll
            for (int q = 0; q < 2; q++) {
                unsigned addr = bsB + s * BS_BYTES +
                    ((unsigned)(wn + (q << 4) + rowB) * 40 + ((chB + (ks << 1)) << 3)) * 2;
                ldsm_x4(bf[q][0], bf[q][1], bf[q][2], bf[q][3], addr);
            }
            #pragma unroll
            for (int mt = 0; mt < 4; mt++)
                #pragma unroll
                for (int nt = 0; nt < 4; nt++) {
                    unsigned bb[2] = { bf[nt >> 1][(nt & 1) << 1],
                                       bf[nt >> 1][((nt & 1) << 1) + 1] };
                    mma_bf16(acc[mt][nt], af[mt], bb);
                }
        }
        __syncthreads();
    }

    #pragma unroll
    for (int mt = 0; mt < 4; mt++) {
        #pragma unroll
        for (int rr = 0; rr < 2; rr++) {
            int m = m0 + wm + (mt << 4) + gq + (rr << 3);
            int b_ = 0, h_ = 0, w_ = 0;
            if constexpr (MODE == 1) {
                int win = m >> 6, n = m & 63;
                b_ = win >> 8;
                int wi = win & 255;
                h_ = ((((wi >> 4) << 3) + (n >> 3)) + 4) & 127;
                w_ = ((((wi & 15) << 3) + (n & 7)) + 4) & 127;
            }
            #pragma unroll
            for (int nt = 0; nt < 4; nt++) {
                int o = o0 + wn + (nt << 3) + (tg << 1);
                float v0 = acc[mt][nt][(rr << 1)];
                float v1 = acc[mt][nt][(rr << 1) + 1];
                if constexpr (MODE == 0) {
                    if (o < 192) { v0 += bias[o]; v1 += bias[o + 1]; }
                    else if (o >= 384) { v0 += bias2[o - 384]; v1 += bias2[o - 383]; }
                    *(bf162*)&g_qkvb[(size_t)m * 576 + o] = __floats2bfloat162_rn(v0, v1);
                } else if constexpr (MODE == 1) {
                    v0 += bias[o];
                    v1 += bias[o + 1];
                    size_t hw = (size_t)(h_ << 7) + w_;
                    v0 += aux[(((size_t)b_ * CCH + o) << 14) + hw];
                    v1 += aux[(((size_t)b_ * CCH + o + 1) << 14) + hw];
                    *(float2*)&g_x1[(size_t)((b_ << 14) + hw) * CCH + o] = make_float2(v0, v1);
                } else if constexpr (MODE == 2) {
                    v0 += bias[o];
                    v1 += bias[o + 1];
                    v0 = 0.5f * v0 * (1.0f + erff(v0 * 0.70710678118654752f));
                    v1 = 0.5f * v1 * (1.0f + erff(v1 * 0.70710678118654752f));
                    *(bf162*)&g_hb[(size_t)m * HID + o] = __floats2bfloat162_rn(v0, v1);
                } else {
                    const float* x1r = g_x1 + (size_t)m * CCH;
                    v0 += bias[o] + x1r[o];
                    v1 += bias[o + 1] + x1r[o + 1];
                    int b = m >> 14, hw = m & 16383;
                    outext[(((size_t)b * CCH + o) << 14) + hw] = v0;
                    outext[(((size_t)b * CCH + o + 1) << 14) + hw] = v1;
                }
            }
        }
    }
}

// ---------------------------------------------------------------------------
extern "C" void kernel_launch(void* const* d_in, const int* in_sizes, int n_in,
                              void* d_out, int out_size) {
    const float* x        = (const float*)d_in[0];
    const float* norm1_w  = (const float*)d_in[1];
    const float* norm1_b  = (const float*)d_in[2];
    const float* qkv_w    = (const float*)d_in[3];
    const float* q_bias   = (const float*)d_in[4];
    const float* v_bias   = (const float*)d_in[5];
    const float* logit_sc = (const float*)d_in[6];
    const float* cpb_w1   = (const float*)d_in[7];
    const float* cpb_b1   = (const float*)d_in[8];
    const float* cpb_w2   = (const float*)d_in[9];
    const float* proj_w   = (const float*)d_in[10];
    const float* proj_b   = (const float*)d_in[11];
    const float* norm2_w  = (const float*)d_in[12];
    const float* norm2_b  = (const float*)d_in[13];
    const float* fc1_w    = (const float*)d_in[14];
    const float* fc1_b    = (const float*)d_in[15];
    const float* fc2_w    = (const float*)d_in[16];
    const float* fc2_b    = (const float*)d_in[17];
    float* out = (float*)d_out;

    bf16 *wq, *wp, *w1, *w2;
    cudaGetSymbolAddress((void**)&wq, g_wqkv);
    cudaGetSymbolAddress((void**)&wp, g_wproj);
    cudaGetSymbolAddress((void**)&w1, g_wfc1);
    cudaGetSymbolAddress((void**)&w2, g_wfc2);

    cvt_w_kernel<<<108, 256>>>(qkv_w, wq);
    cvt_w_kernel<<<36, 256>>>(proj_w, wp);
    cvt_w_kernel<<<144, 256>>>(fc1_w, w1);
    cvt_w_kernel<<<144, 256>>>(fc2_w, w2);
    cpb_table_kernel<<<225, 512>>>(cpb_w1, cpb_b1, cpb_w2);
    rpbias_kernel<<<96, 256>>>();
    ln1_kernel<<<TOK / 32, 192>>>(x, norm1_w, norm1_b);
    gemm_kernel<0><<<dim3(9, TOK / 256), 256>>>(wq, q_bias, v_bias, nullptr, nullptr);
    attn_kernel<<<dim3(HEADS, NWIN), 128>>>(logit_sc);
    gemm_kernel<1><<<dim3(3, TOK / 256), 256>>>(wp, proj_b, nullptr, x, nullptr);
    ln2_kernel<<<TOK / 8, 256>>>(norm2_w, norm2_b);
    gemm_kernel<2><<<dim3(12, TOK / 256), 256>>>(w1, fc1_b, nullptr, nullptr, nullptr);
    gemm_kernel<3><<<dim3(3, TOK / 256), 256>>>(w2, fc2_b, nullptr, nullptr, out);
}